// round 12
// baseline (speedup 1.0000x reference)
#include <cuda_runtime.h>
#include <cuda_fp16.h>
#include <math.h>

#define TINF 3.0e38f
#define TT   1024
#define BB   32
#define DDIM 64
#define RS   1024        // halves per diag row
#define DROWS 2048       // rows 0..2046 used; predicate caps loads at 2047

// Diag-major SQUARED cost [b][d][j] in fp16 (DP runs on d^2; sqrt applied to
// the final per-batch scalar — max/min commute with monotone sqrt).
// Valid cells written by cost_kernel; the ~2 boundary cells per row
// (j=d+1, j=d-1024) pre-set +inf by binit_kernel. Deep-invalid cells stay
// uninitialized: provably never reach a valid cell (fmin/fmax NaN-safe).
__device__ __half g_cost[(size_t)BB * DROWS * RS];
__device__ float g_n2[2 * BB * TT];
__device__ float g_bdist[BB];

// ---------------------------------------------------------------------------
// Kernel 0: boundary-only init (half +inf = 0x7C00). 65K scalar writes.
// ---------------------------------------------------------------------------
__global__ void binit_kernel() {
    int i = blockIdx.x * blockDim.x + threadIdx.x;
    int b = i >> 11, d = i & 2047;
    if (b >= BB) return;
    unsigned short* row = (unsigned short*)(g_cost + ((size_t)b * DROWS + d) * RS);
    if (d <= 1022)                   row[d + 1]    = 0x7C00;
    else if (d >= 1024 && d <= 2046) row[d - 1024] = 0x7C00;
}

// ---------------------------------------------------------------------------
// Kernel 1: squared row norms. One warp per 64-dim row.
// ---------------------------------------------------------------------------
__global__ void norms_kernel(const float* __restrict__ pred,
                             const float* __restrict__ targ) {
    int gw   = (blockIdx.x * blockDim.x + threadIdx.x) >> 5;
    int lane = threadIdx.x & 31;
    if (gw >= 2 * BB * TT) return;
    const float* src = (gw < BB * TT) ? (pred + (size_t)gw * DDIM)
                                      : (targ + (size_t)(gw - BB * TT) * DDIM);
    float x0 = src[lane], x1 = src[lane + 32];
    float s = x0 * x0 + x1 * x1;
    #pragma unroll
    for (int o = 16; o > 0; o >>= 1) s += __shfl_down_sync(0xffffffffu, s, o);
    if (lane == 0) g_n2[gw] = s;
}

// ---------------------------------------------------------------------------
// Kernel 2: TF32 tensor-core cost tiles; writes d^2 as __half (no sqrt).
// ---------------------------------------------------------------------------
__device__ __forceinline__ unsigned f2tf(float x) {
    unsigned u;
    asm("cvt.rna.tf32.f32 %0, %1;" : "=r"(u) : "f"(x));
    return u;
}
__device__ __forceinline__ void mma_tf32(float c[4], const unsigned a[4],
                                         const unsigned b[2]) {
    asm volatile(
        "mma.sync.aligned.m16n8k8.row.col.f32.tf32.tf32.f32 "
        "{%0,%1,%2,%3}, {%4,%5,%6,%7}, {%8,%9}, {%0,%1,%2,%3};"
        : "+f"(c[0]), "+f"(c[1]), "+f"(c[2]), "+f"(c[3])
        : "r"(a[0]), "r"(a[1]), "r"(a[2]), "r"(a[3]), "r"(b[0]), "r"(b[1]));
}

#define SKP 36   // smem k-stride (32 + 4 pad)

__global__ void __launch_bounds__(256, 2) cost_kernel(const float* __restrict__ pred,
                                                      const float* __restrict__ targ) {
    int b  = blockIdx.z;
    int i0 = blockIdx.y * 128, j0 = blockIdx.x * 128;
    const float* A  = pred + (size_t)b * TT * DDIM;
    const float* Bm = targ + (size_t)b * TT * DDIM;

    __shared__ __align__(16) float smbuf[2 * 128 * SKP];   // 36864 B
    float* sA = smbuf;
    float* sB = smbuf + 128 * SKP;
    float* Cs = smbuf;                                     // reused in epilogue

    int tid  = threadIdx.x;
    int lane = tid & 31, w = tid >> 5;
    int g    = lane >> 2, tig = lane & 3;
    int wm   = (w & 3) * 32, wn = (w >> 2) * 64;

    float c[2][8][4];
    #pragma unroll
    for (int mt = 0; mt < 2; ++mt)
        #pragma unroll
        for (int nt = 0; nt < 8; ++nt)
            #pragma unroll
            for (int e = 0; e < 4; ++e) c[mt][nt][e] = 0.f;

    int lr = tid >> 1;
    int lk = (tid & 1) * 16;
    const float* ga = A  + (size_t)(i0 + lr) * DDIM + lk;
    const float* gb = Bm + (size_t)(j0 + lr) * DDIM + lk;

    #pragma unroll 1
    for (int kc = 0; kc < 64; kc += 32) {
        #pragma unroll
        for (int c4 = 0; c4 < 4; ++c4) {
            float4 va = *(const float4*)(ga + kc + c4 * 4);
            float4 vb = *(const float4*)(gb + kc + c4 * 4);
            int o = lr * SKP + lk + c4 * 4;
            sA[o + 0] = __uint_as_float(f2tf(va.x));
            sA[o + 1] = __uint_as_float(f2tf(va.y));
            sA[o + 2] = __uint_as_float(f2tf(va.z));
            sA[o + 3] = __uint_as_float(f2tf(va.w));
            sB[o + 0] = __uint_as_float(f2tf(vb.x));
            sB[o + 1] = __uint_as_float(f2tf(vb.y));
            sB[o + 2] = __uint_as_float(f2tf(vb.z));
            sB[o + 3] = __uint_as_float(f2tf(vb.w));
        }
        __syncthreads();

        #pragma unroll
        for (int ks = 0; ks < 32; ks += 8) {
            unsigned af[2][4], bf[8][2];
            #pragma unroll
            for (int mt = 0; mt < 2; ++mt) {
                int mr = wm + mt * 16;
                af[mt][0] = __float_as_uint(sA[(mr + g)     * SKP + ks + tig]);
                af[mt][1] = __float_as_uint(sA[(mr + g + 8) * SKP + ks + tig]);
                af[mt][2] = __float_as_uint(sA[(mr + g)     * SKP + ks + tig + 4]);
                af[mt][3] = __float_as_uint(sA[(mr + g + 8) * SKP + ks + tig + 4]);
            }
            #pragma unroll
            for (int nt = 0; nt < 8; ++nt) {
                int nr = wn + nt * 8 + g;
                bf[nt][0] = __float_as_uint(sB[nr * SKP + ks + tig]);
                bf[nt][1] = __float_as_uint(sB[nr * SKP + ks + tig + 4]);
            }
            #pragma unroll
            for (int mt = 0; mt < 2; ++mt)
                #pragma unroll
                for (int nt = 0; nt < 8; ++nt)
                    mma_tf32(c[mt][nt], af[mt], bf[nt]);
        }
        __syncthreads();
    }

    float a2v[2][2], b2v[8][2];
    #pragma unroll
    for (int mt = 0; mt < 2; ++mt) {
        a2v[mt][0] = g_n2[b * TT + i0 + wm + mt * 16 + g];
        a2v[mt][1] = g_n2[b * TT + i0 + wm + mt * 16 + g + 8];
    }
    #pragma unroll
    for (int nt = 0; nt < 8; ++nt) {
        b2v[nt][0] = g_n2[BB * TT + b * TT + j0 + wn + nt * 8 + 2 * tig];
        b2v[nt][1] = g_n2[BB * TT + b * TT + j0 + wn + nt * 8 + 2 * tig + 1];
    }

    __half* out = g_cost + (size_t)b * DROWS * RS;

    #pragma unroll 1
    for (int qq = 0; qq < 4; ++qq) {
        int qi = qq >> 1, qj = qq & 1;
        __syncthreads();
        if ((w >> 2) == qj && ((w & 3) >> 1) == qi) {
            int mloc0 = ((w & 3) & 1) * 32;
            #pragma unroll
            for (int mt = 0; mt < 2; ++mt) {
                int ml = mloc0 + mt * 16 + g;
                #pragma unroll
                for (int nt = 0; nt < 8; ++nt) {
                    int nl = nt * 8 + 2 * tig;
                    float s0 = a2v[mt][0] + b2v[nt][0] - 2.0f * c[mt][nt][0];
                    float s1 = a2v[mt][0] + b2v[nt][1] - 2.0f * c[mt][nt][1];
                    float s2 = a2v[mt][1] + b2v[nt][0] - 2.0f * c[mt][nt][2];
                    float s3 = a2v[mt][1] + b2v[nt][1] - 2.0f * c[mt][nt][3];
                    Cs[ml * 66 + nl]           = fmaxf(s0, 1e-12f);
                    Cs[ml * 66 + nl + 1]       = fmaxf(s1, 1e-12f);
                    Cs[(ml + 8) * 66 + nl]     = fmaxf(s2, 1e-12f);
                    Cs[(ml + 8) * 66 + nl + 1] = fmaxf(s3, 1e-12f);
                }
            }
        }
        __syncthreads();

        int i0q = i0 + qi * 64, j0q = j0 + qj * 64;
        int D0 = i0q + j0q;
        for (int dd = w; dd < 127; dd += 8) {
            int jl = max(0, dd - 63);
            int jh = min(dd, 63);
            int L = jh - jl + 1;
            size_t gbase = (size_t)(D0 + dd) * RS + (size_t)(j0q + jl);
            for (int l = lane; l < L; l += 32) {
                int j = jl + l;
                out[gbase + l] = __float2half(Cs[(dd - j) * 66 + j]);
            }
        }
    }
}

// ---------------------------------------------------------------------------
// Kernel 3: wavefront DP on fp16 squared costs. smem traffic per superstep
// cut 64KB -> ~25KB (was crossbar-bound): fp16 staging halves CC+fill bytes;
// p/q halo moved to shfl_up (registers hold last superstep's D/C) with an
// 8-slot double-buffered warp-boundary mailbox. Compute stays fp32
// (conversion on load); DP is pure selection so fp16 adds only input
// quantization. Band predication + boundary-inf semantics unchanged (R11).
// ---------------------------------------------------------------------------
#define RING    10
#define SROWH   1032                   // halves per staged row (4 guard + 1024 + 4 pad)
#define SSTAGEH (4 * SROWH)            // halves per stage
#define DPDYN   (RING * SSTAGEH * 2)   // dynamic smem bytes (82,560)

__device__ __forceinline__ void cpa8(unsigned dst, const __half* src) {
    asm volatile("cp.async.ca.shared.global [%0], [%1], 8;"
                 :: "r"(dst), "l"(src));
}

__global__ void __launch_bounds__(256, 1) dp_kernel() {
    extern __shared__ __half dsmh[];
    int b    = blockIdx.x;
    int t    = threadIdx.x;
    int w    = t >> 5;
    int lane = t & 31;
    int j0   = t << 2;
    const __half* SC = g_cost + (size_t)b * DROWS * RS;

    __shared__ float4 swp[2][8], swq[2][8];   // warp-boundary mailboxes
    if (t < 16)      ((float4*)swp)[t]      = make_float4(TINF, TINF, TINF, TINF);
    else if (t < 32) ((float4*)swq)[t - 16] = make_float4(TINF, TINF, TINF, TINF);
    for (int i = t; i < RING * 4; i += 256) {             // per-row inf guards
        unsigned* gr = (unsigned*)(dsmh + i * SROWH);
        gr[0] = 0x7C007C00u; gr[1] = 0x7C007C00u;
    }
    __syncthreads();

    unsigned smu = (unsigned)__cvta_generic_to_shared(dsmh) + (unsigned)(4 + j0) * 2;

    // Band predicate: row d useful for this thread iff d in [j0-1, j0+1027].
    #define DP_ON(d) ((unsigned)((d) - j0 + 1) <= 1028u)

    // Prologue: issue stages 0..8 (one commit group per stage).
    for (int s = 0; s < RING - 1; ++s) {
        const __half* src = SC + (size_t)(4 * s) * RS + j0;
        unsigned d = smu + s * (SSTAGEH * 2);
        #pragma unroll
        for (int k = 0; k < 4; ++k)
            if (DP_ON(4 * s + k)) cpa8(d + k * (SROWH * 2), src + (size_t)k * RS);
        asm volatile("cp.async.commit_group;");
    }

    float p0 = TINF, p1 = TINF, p2 = TINF, p3 = TINF;   // diag d0-1, own cols
    float q0 = TINF, q1 = TINF, q2 = TINF, q3 = TINF;   // diag d0-2, own cols
    float res  = 0.f;
    int stage  = 0;

    // 512 supersteps x 4 diagonals; res latched at s=511 (diag 2046).
    #pragma unroll 1
    for (int s = 0; s < 512; ++s) {
        asm volatile("cp.async.wait_group 8;");
        __syncthreads();                       // stage s + mailboxes visible

        const __half* bp = dsmh + stage * SSTAGEH;
        float CC[4][8];
        #pragma unroll
        for (int k = 0; k < 4; ++k) {
            uint2 hv = *(const uint2*)(bp + k * SROWH + j0);       // cols j0-4..j0-1
            uint2 ov = *(const uint2*)(bp + k * SROWH + j0 + 4);   // cols j0..j0+3
            __half2 h0 = *(__half2*)&hv.x, h1 = *(__half2*)&hv.y;
            __half2 o0 = *(__half2*)&ov.x, o1 = *(__half2*)&ov.y;
            CC[k][0] = __low2float(h0);  CC[k][1] = __high2float(h0);
            CC[k][2] = __low2float(h1);  CC[k][3] = __high2float(h1);
            CC[k][4] = __low2float(o0);  CC[k][5] = __high2float(o0);
            CC[k][6] = __low2float(o1);  CC[k][7] = __high2float(o1);
        }

        // p/q halo: left neighbor's registers (they hold last superstep's D/C).
        float hp0 = __shfl_up_sync(0xffffffffu, p0, 1);
        float hp1 = __shfl_up_sync(0xffffffffu, p1, 1);
        float hp2 = __shfl_up_sync(0xffffffffu, p2, 1);
        float hp3 = __shfl_up_sync(0xffffffffu, p3, 1);
        float hq0 = __shfl_up_sync(0xffffffffu, q0, 1);
        float hq1 = __shfl_up_sync(0xffffffffu, q1, 1);
        float hq2 = __shfl_up_sync(0xffffffffu, q2, 1);
        float hq3 = __shfl_up_sync(0xffffffffu, q3, 1);
        if (lane == 0) {
            if (w == 0) {
                hp0 = hp1 = hp2 = hp3 = TINF;
                hq0 = hq1 = hq2 = TINF;
                hq3 = (s == 0) ? -TINF : TINF;          // seed: virtual ca[-1][-1]
            } else {
                float4 a = swp[s & 1][w - 1], c4 = swq[s & 1][w - 1];
                hp0 = a.x;  hp1 = a.y;  hp2 = a.z;  hp3 = a.w;
                hq0 = c4.x; hq1 = c4.y; hq2 = c4.z; hq3 = c4.w;
            }
        }

        float P[8] = {hp0, hp1, hp2, hp3, p0, p1, p2, p3};
        float Q[8] = {hq0, hq1, hq2, hq3, q0, q1, q2, q3};

        float A[8], B[8], C[8], D[8];
        #pragma unroll
        for (int i = 1; i < 8; ++i)
            A[i] = fmaxf(CC[0][i], fminf(fminf(P[i], P[i-1]), Q[i-1]));
        #pragma unroll
        for (int i = 2; i < 8; ++i)
            B[i] = fmaxf(CC[1][i], fminf(fminf(A[i], A[i-1]), P[i-1]));
        #pragma unroll
        for (int i = 3; i < 8; ++i)
            C[i] = fmaxf(CC[2][i], fminf(fminf(B[i], B[i-1]), A[i-1]));
        #pragma unroll
        for (int i = 4; i < 8; ++i)
            D[i] = fmaxf(CC[3][i], fminf(fminf(C[i], C[i-1]), B[i-1]));

        if (lane == 31) {
            swp[(s + 1) & 1][w] = make_float4(D[4], D[5], D[6], D[7]);
            swq[(s + 1) & 1][w] = make_float4(C[4], C[5], C[6], C[7]);
        }
        if (s == 511) res = C[7];              // diag 2046, col 1023 @ t=255 (d^2)

        p0 = D[4]; p1 = D[5]; p2 = D[6]; p3 = D[7];
        q0 = C[4]; q1 = C[5]; q2 = C[6]; q3 = C[7];

        // Issue stage s+9 into the buffer consumed at body s-1 (race-free).
        {
            int st2 = stage + (RING - 1); if (st2 >= RING) st2 -= RING;
            int dbase = 4 * (s + RING - 1);
            const __half* src = SC + (size_t)dbase * RS + j0;
            unsigned d = smu + st2 * (SSTAGEH * 2);
            #pragma unroll
            for (int k = 0; k < 4; ++k)
                if (DP_ON(dbase + k)) cpa8(d + k * (SROWH * 2), src + (size_t)k * RS);
            asm volatile("cp.async.commit_group;");
        }
        if (++stage == RING) stage = 0;
    }

    if (t == 255) g_bdist[b] = res;
    #undef DP_ON
}

// ---------------------------------------------------------------------------
// Kernel 4: sqrt of per-batch squared Frechet, then mean.
// ---------------------------------------------------------------------------
__global__ void reduce_kernel(float* out) {
    float v = sqrtf(g_bdist[threadIdx.x]);
    #pragma unroll
    for (int o = 16; o > 0; o >>= 1) v += __shfl_down_sync(0xffffffffu, v, o);
    if (threadIdx.x == 0) out[0] = v * (1.0f / BB);
}

// ---------------------------------------------------------------------------
extern "C" void kernel_launch(void* const* d_in, const int* in_sizes, int n_in,
                              void* d_out, int out_size) {
    const float* pred = (const float*)d_in[0];
    const float* targ = (const float*)d_in[1];
    (void)in_sizes; (void)n_in; (void)out_size;

    cudaFuncSetAttribute(dp_kernel,
                         cudaFuncAttributeMaxDynamicSharedMemorySize, DPDYN);

    binit_kernel<<<256, 256>>>();
    norms_kernel<<<8192, 256>>>(pred, targ);
    dim3 cg(8, 8, 32);
    cost_kernel<<<cg, 256>>>(pred, targ);
    dp_kernel<<<32, 256, DPDYN>>>();
    reduce_kernel<<<1, 32>>>((float*)d_out);
}

// round 13
// speedup vs baseline: 1.3213x; 1.3213x over previous
#include <cuda_runtime.h>
#include <cuda_fp16.h>
#include <math.h>

#define TINF 3.0e38f
#define TT   1024
#define BB   32
#define DDIM 64
#define RS   1024        // halves per diag row
#define DROWS 2048       // rows 0..2046 used; predicate caps loads at 2047

// Diag-major SQUARED cost [b][d][j] in fp16 (DP runs on d^2; sqrt on the final
// per-batch scalar). Valid cells written by cost role; 2 boundary cells per row
// pre-set +inf by binit. Deep-invalid cells unreachable (fmin/fmax NaN-safe).
__device__ __half g_cost[(size_t)BB * DROWS * RS];
__device__ float g_n2[2 * BB * TT];
__device__ float g_bdist[BB];
__device__ int   g_cnt[BB * 15];     // finished tiles per (batch, tile-antidiag)

// Tile visit order: (it,jt) sorted by g=it+jt (it*8+jt encoded).
__device__ const unsigned char g_order[64] = {
    0,
    1, 8,
    2, 9, 16,
    3, 10, 17, 24,
    4, 11, 18, 25, 32,
    5, 12, 19, 26, 33, 40,
    6, 13, 20, 27, 34, 41, 48,
    7, 14, 21, 28, 35, 42, 49, 56,
    15, 22, 29, 36, 43, 50, 57,
    23, 30, 37, 44, 51, 58,
    31, 38, 45, 52, 59,
    39, 46, 53, 60,
    47, 54, 61,
    55, 62,
    63
};

// ---------------------------------------------------------------------------
// Kernel 0: boundary-only init (+ zero the progress counters each launch).
// ---------------------------------------------------------------------------
__global__ void binit_kernel() {
    int i = blockIdx.x * blockDim.x + threadIdx.x;
    if (i < BB * 15) g_cnt[i] = 0;
    int b = i >> 11, d = i & 2047;
    if (b >= BB) return;
    unsigned short* row = (unsigned short*)(g_cost + ((size_t)b * DROWS + d) * RS);
    if (d <= 1022)                   row[d + 1]    = 0x7C00;
    else if (d >= 1024 && d <= 2046) row[d - 1024] = 0x7C00;
}

// ---------------------------------------------------------------------------
// Kernel 1: squared row norms. One warp per 64-dim row.
// ---------------------------------------------------------------------------
__global__ void norms_kernel(const float* __restrict__ pred,
                             const float* __restrict__ targ) {
    int gw   = (blockIdx.x * blockDim.x + threadIdx.x) >> 5;
    int lane = threadIdx.x & 31;
    if (gw >= 2 * BB * TT) return;
    const float* src = (gw < BB * TT) ? (pred + (size_t)gw * DDIM)
                                      : (targ + (size_t)(gw - BB * TT) * DDIM);
    float x0 = src[lane], x1 = src[lane + 32];
    float s = x0 * x0 + x1 * x1;
    #pragma unroll
    for (int o = 16; o > 0; o >>= 1) s += __shfl_down_sync(0xffffffffu, s, o);
    if (lane == 0) g_n2[gw] = s;
}

// ---------------------------------------------------------------------------
// TF32 mma helpers.
// ---------------------------------------------------------------------------
__device__ __forceinline__ unsigned f2tf(float x) {
    unsigned u;
    asm("cvt.rna.tf32.f32 %0, %1;" : "=r"(u) : "f"(x));
    return u;
}
__device__ __forceinline__ void mma_tf32(float c[4], const unsigned a[4],
                                         const unsigned b[2]) {
    asm volatile(
        "mma.sync.aligned.m16n8k8.row.col.f32.tf32.tf32.f32 "
        "{%0,%1,%2,%3}, {%4,%5,%6,%7}, {%8,%9}, {%0,%1,%2,%3};"
        : "+f"(c[0]), "+f"(c[1]), "+f"(c[2]), "+f"(c[3])
        : "r"(a[0]), "r"(a[1]), "r"(a[2]), "r"(a[3]), "r"(b[0]), "r"(b[1]));
}

#define SKP 36
#define RING    10
#define SROWH   1032                   // halves per staged row (4 guard + 1024 + 4 pad)
#define SSTAGEH (4 * SROWH)
#define DPDYN   (RING * SSTAGEH * 2)   // 82,560 B dynamic -> 2 CTAs/SM

__device__ __forceinline__ void cpa8(unsigned dst, const __half* src) {
    asm volatile("cp.async.ca.shared.global [%0], [%1], 8;"
                 :: "r"(dst), "l"(src));
}

// ---------------------------------------------------------------------------
// Cost role: TF32 tiles -> fp16 d^2, diag-major. Releases its tile via
// fence + atomicAdd on g_cnt[b][it+jt].
// ---------------------------------------------------------------------------
__device__ void cost_role(char* dyn, const float* __restrict__ pred,
                          const float* __restrict__ targ, int cbid) {
    int b  = cbid & 31;
    int code = g_order[cbid >> 5];
    int it = code >> 3, jt = code & 7;
    int i0 = it * 128, j0 = jt * 128;
    const float* A  = pred + (size_t)b * TT * DDIM;
    const float* Bm = targ + (size_t)b * TT * DDIM;

    float* smbuf = (float*)dyn;          // 36,864 B of the 82,560 dynamic
    float* sA = smbuf;
    float* sB = smbuf + 128 * SKP;
    float* Cs = smbuf;

    int tid  = threadIdx.x;
    int lane = tid & 31, w = tid >> 5;
    int g    = lane >> 2, tig = lane & 3;
    int wm   = (w & 3) * 32, wn = (w >> 2) * 64;

    float c[2][8][4];
    #pragma unroll
    for (int mt = 0; mt < 2; ++mt)
        #pragma unroll
        for (int nt = 0; nt < 8; ++nt)
            #pragma unroll
            for (int e = 0; e < 4; ++e) c[mt][nt][e] = 0.f;

    int lr = tid >> 1;
    int lk = (tid & 1) * 16;
    const float* ga = A  + (size_t)(i0 + lr) * DDIM + lk;
    const float* gb = Bm + (size_t)(j0 + lr) * DDIM + lk;

    #pragma unroll 1
    for (int kc = 0; kc < 64; kc += 32) {
        #pragma unroll
        for (int c4 = 0; c4 < 4; ++c4) {
            float4 va = *(const float4*)(ga + kc + c4 * 4);
            float4 vb = *(const float4*)(gb + kc + c4 * 4);
            int o = lr * SKP + lk + c4 * 4;
            sA[o + 0] = __uint_as_float(f2tf(va.x));
            sA[o + 1] = __uint_as_float(f2tf(va.y));
            sA[o + 2] = __uint_as_float(f2tf(va.z));
            sA[o + 3] = __uint_as_float(f2tf(va.w));
            sB[o + 0] = __uint_as_float(f2tf(vb.x));
            sB[o + 1] = __uint_as_float(f2tf(vb.y));
            sB[o + 2] = __uint_as_float(f2tf(vb.z));
            sB[o + 3] = __uint_as_float(f2tf(vb.w));
        }
        __syncthreads();

        #pragma unroll
        for (int ks = 0; ks < 32; ks += 8) {
            unsigned af[2][4], bf[8][2];
            #pragma unroll
            for (int mt = 0; mt < 2; ++mt) {
                int mr = wm + mt * 16;
                af[mt][0] = __float_as_uint(sA[(mr + g)     * SKP + ks + tig]);
                af[mt][1] = __float_as_uint(sA[(mr + g + 8) * SKP + ks + tig]);
                af[mt][2] = __float_as_uint(sA[(mr + g)     * SKP + ks + tig + 4]);
                af[mt][3] = __float_as_uint(sA[(mr + g + 8) * SKP + ks + tig + 4]);
            }
            #pragma unroll
            for (int nt = 0; nt < 8; ++nt) {
                int nr = wn + nt * 8 + g;
                bf[nt][0] = __float_as_uint(sB[nr * SKP + ks + tig]);
                bf[nt][1] = __float_as_uint(sB[nr * SKP + ks + tig + 4]);
            }
            #pragma unroll
            for (int mt = 0; mt < 2; ++mt)
                #pragma unroll
                for (int nt = 0; nt < 8; ++nt)
                    mma_tf32(c[mt][nt], af[mt], bf[nt]);
        }
        __syncthreads();
    }

    float a2v[2][2], b2v[8][2];
    #pragma unroll
    for (int mt = 0; mt < 2; ++mt) {
        a2v[mt][0] = g_n2[b * TT + i0 + wm + mt * 16 + g];
        a2v[mt][1] = g_n2[b * TT + i0 + wm + mt * 16 + g + 8];
    }
    #pragma unroll
    for (int nt = 0; nt < 8; ++nt) {
        b2v[nt][0] = g_n2[BB * TT + b * TT + j0 + wn + nt * 8 + 2 * tig];
        b2v[nt][1] = g_n2[BB * TT + b * TT + j0 + wn + nt * 8 + 2 * tig + 1];
    }

    __half* out = g_cost + (size_t)b * DROWS * RS;

    #pragma unroll 1
    for (int qq = 0; qq < 4; ++qq) {
        int qi = qq >> 1, qj = qq & 1;
        __syncthreads();
        if ((w >> 2) == qj && ((w & 3) >> 1) == qi) {
            int mloc0 = ((w & 3) & 1) * 32;
            #pragma unroll
            for (int mt = 0; mt < 2; ++mt) {
                int ml = mloc0 + mt * 16 + g;
                #pragma unroll
                for (int nt = 0; nt < 8; ++nt) {
                    int nl = nt * 8 + 2 * tig;
                    float s0 = a2v[mt][0] + b2v[nt][0] - 2.0f * c[mt][nt][0];
                    float s1 = a2v[mt][0] + b2v[nt][1] - 2.0f * c[mt][nt][1];
                    float s2 = a2v[mt][1] + b2v[nt][0] - 2.0f * c[mt][nt][2];
                    float s3 = a2v[mt][1] + b2v[nt][1] - 2.0f * c[mt][nt][3];
                    Cs[ml * 66 + nl]           = fmaxf(s0, 1e-12f);
                    Cs[ml * 66 + nl + 1]       = fmaxf(s1, 1e-12f);
                    Cs[(ml + 8) * 66 + nl]     = fmaxf(s2, 1e-12f);
                    Cs[(ml + 8) * 66 + nl + 1] = fmaxf(s3, 1e-12f);
                }
            }
        }
        __syncthreads();

        int i0q = i0 + qi * 64, j0q = j0 + qj * 64;
        int D0 = i0q + j0q;
        for (int dd = w; dd < 127; dd += 8) {
            int jl = max(0, dd - 63);
            int jh = min(dd, 63);
            int L = jh - jl + 1;
            size_t gbase = (size_t)(D0 + dd) * RS + (size_t)(j0q + jl);
            for (int l = lane; l < L; l += 32) {
                int j = jl + l;
                out[gbase + l] = __float2half(Cs[(dd - j) * 66 + j]);
            }
        }
    }

    // Release: all writes gpu-visible, then bump the tile-group counter.
    __threadfence();
    __syncthreads();
    if (tid == 0) atomicAdd(&g_cnt[b * 15 + (it + jt)], 1);
}

// ---------------------------------------------------------------------------
// DP role: R12 dp verbatim + rare availability polls (15 events total).
// ---------------------------------------------------------------------------
__device__ void dp_role(char* dyn) {
    __half* dsmh = (__half*)dyn;
    int b    = blockIdx.x;
    int t    = threadIdx.x;
    int w    = t >> 5;
    int lane = t & 31;
    int j0   = t << 2;
    const __half* SC = g_cost + (size_t)b * DROWS * RS;

    __shared__ float4 swp[2][8], swq[2][8];
    if (t < 16)      ((float4*)swp)[t]      = make_float4(TINF, TINF, TINF, TINF);
    else if (t < 32) ((float4*)swq)[t - 16] = make_float4(TINF, TINF, TINF, TINF);
    for (int i = t; i < RING * 4; i += 256) {
        unsigned* gr = (unsigned*)(dsmh + i * SROWH);
        gr[0] = 0x7C007C00u; gr[1] = 0x7C007C00u;
    }
    __syncthreads();

    unsigned smu = (unsigned)__cvta_generic_to_shared(dsmh) + (unsigned)(4 + j0) * 2;

    #define DP_ON(d) ((unsigned)((d) - j0 + 1) <= 1028u)

    // Availability: rows <= 128*G+127 ready once all tile-groups <= G done.
    int done_groups = 0;
    const volatile int* cnt = (const volatile int*)(g_cnt + b * 15);
    // Prologue needs rows <= 35 -> group 0.
    while (done_groups <= 0) {
        if (cnt[0] >= 1) done_groups = 1;
    }
    __threadfence();

    for (int s = 0; s < RING - 1; ++s) {
        const __half* src = SC + (size_t)(4 * s) * RS + j0;
        unsigned d = smu + s * (SSTAGEH * 2);
        #pragma unroll
        for (int k = 0; k < 4; ++k)
            if (DP_ON(4 * s + k)) cpa8(d + k * (SROWH * 2), src + (size_t)k * RS);
        asm volatile("cp.async.commit_group;");
    }

    float p0 = TINF, p1 = TINF, p2 = TINF, p3 = TINF;
    float q0 = TINF, q1 = TINF, q2 = TINF, q3 = TINF;
    float res  = 0.f;
    int stage  = 0;

    #pragma unroll 1
    for (int s = 0; s < 512; ++s) {
        asm volatile("cp.async.wait_group 8;");
        __syncthreads();

        const __half* bp = dsmh + stage * SSTAGEH;
        float CC[4][8];
        #pragma unroll
        for (int k = 0; k < 4; ++k) {
            uint2 hv = *(const uint2*)(bp + k * SROWH + j0);
            uint2 ov = *(const uint2*)(bp + k * SROWH + j0 + 4);
            __half2 h0 = *(__half2*)&hv.x, h1 = *(__half2*)&hv.y;
            __half2 o0 = *(__half2*)&ov.x, o1 = *(__half2*)&ov.y;
            CC[k][0] = __low2float(h0);  CC[k][1] = __high2float(h0);
            CC[k][2] = __low2float(h1);  CC[k][3] = __high2float(h1);
            CC[k][4] = __low2float(o0);  CC[k][5] = __high2float(o0);
            CC[k][6] = __low2float(o1);  CC[k][7] = __high2float(o1);
        }

        float hp0 = __shfl_up_sync(0xffffffffu, p0, 1);
        float hp1 = __shfl_up_sync(0xffffffffu, p1, 1);
        float hp2 = __shfl_up_sync(0xffffffffu, p2, 1);
        float hp3 = __shfl_up_sync(0xffffffffu, p3, 1);
        float hq0 = __shfl_up_sync(0xffffffffu, q0, 1);
        float hq1 = __shfl_up_sync(0xffffffffu, q1, 1);
        float hq2 = __shfl_up_sync(0xffffffffu, q2, 1);
        float hq3 = __shfl_up_sync(0xffffffffu, q3, 1);
        if (lane == 0) {
            if (w == 0) {
                hp0 = hp1 = hp2 = hp3 = TINF;
                hq0 = hq1 = hq2 = TINF;
                hq3 = (s == 0) ? -TINF : TINF;          // seed: virtual ca[-1][-1]
            } else {
                float4 a = swp[s & 1][w - 1], c4 = swq[s & 1][w - 1];
                hp0 = a.x;  hp1 = a.y;  hp2 = a.z;  hp3 = a.w;
                hq0 = c4.x; hq1 = c4.y; hq2 = c4.z; hq3 = c4.w;
            }
        }

        float P[8] = {hp0, hp1, hp2, hp3, p0, p1, p2, p3};
        float Q[8] = {hq0, hq1, hq2, hq3, q0, q1, q2, q3};

        float A[8], B[8], C[8], D[8];
        #pragma unroll
        for (int i = 1; i < 8; ++i)
            A[i] = fmaxf(CC[0][i], fminf(fminf(P[i], P[i-1]), Q[i-1]));
        #pragma unroll
        for (int i = 2; i < 8; ++i)
            B[i] = fmaxf(CC[1][i], fminf(fminf(A[i], A[i-1]), P[i-1]));
        #pragma unroll
        for (int i = 3; i < 8; ++i)
            C[i] = fmaxf(CC[2][i], fminf(fminf(B[i], B[i-1]), A[i-1]));
        #pragma unroll
        for (int i = 4; i < 8; ++i)
            D[i] = fmaxf(CC[3][i], fminf(fminf(C[i], C[i-1]), B[i-1]));

        if (lane == 31) {
            swp[(s + 1) & 1][w] = make_float4(D[4], D[5], D[6], D[7]);
            swq[(s + 1) & 1][w] = make_float4(C[4], C[5], C[6], C[7]);
        }
        if (s == 511) res = C[7];

        p0 = D[4]; p1 = D[5]; p2 = D[6]; p3 = D[7];
        q0 = C[4]; q1 = C[5]; q2 = C[6]; q3 = C[7];

        // Availability check for the rows about to be issued (rows <= 4s+39).
        {
            int gneed = (4 * s + 39) >> 7;
            if (gneed > 14) gneed = 14;
            if (done_groups <= gneed) {
                while (done_groups <= gneed) {
                    int tn = (done_groups <= 7) ? done_groups + 1 : 15 - done_groups;
                    if (cnt[done_groups] >= tn) ++done_groups;
                }
                __threadfence();
            }
        }

        {
            int st2 = stage + (RING - 1); if (st2 >= RING) st2 -= RING;
            int dbase = 4 * (s + RING - 1);
            const __half* src = SC + (size_t)dbase * RS + j0;
            unsigned d = smu + st2 * (SSTAGEH * 2);
            #pragma unroll
            for (int k = 0; k < 4; ++k)
                if (DP_ON(dbase + k)) cpa8(d + k * (SROWH * 2), src + (size_t)k * RS);
            asm volatile("cp.async.commit_group;");
        }
        if (++stage == RING) stage = 0;
    }

    if (t == 255) g_bdist[b] = res;
    #undef DP_ON
}

// ---------------------------------------------------------------------------
// Fused kernel: bids 0..31 = DP consumers (wave-1 resident; never block
// producers => no deadlock), bids 32..2079 = cost producers.
// ---------------------------------------------------------------------------
__global__ void __launch_bounds__(256, 2) fused_kernel(const float* __restrict__ pred,
                                                       const float* __restrict__ targ) {
    extern __shared__ __align__(16) char dyn[];
    if (blockIdx.x < 32) dp_role(dyn);
    else                 cost_role(dyn, pred, targ, blockIdx.x - 32);
}

// ---------------------------------------------------------------------------
// Kernel 4: sqrt of per-batch squared Frechet, then mean.
// ---------------------------------------------------------------------------
__global__ void reduce_kernel(float* out) {
    float v = sqrtf(g_bdist[threadIdx.x]);
    #pragma unroll
    for (int o = 16; o > 0; o >>= 1) v += __shfl_down_sync(0xffffffffu, v, o);
    if (threadIdx.x == 0) out[0] = v * (1.0f / BB);
}

// ---------------------------------------------------------------------------
extern "C" void kernel_launch(void* const* d_in, const int* in_sizes, int n_in,
                              void* d_out, int out_size) {
    const float* pred = (const float*)d_in[0];
    const float* targ = (const float*)d_in[1];
    (void)in_sizes; (void)n_in; (void)out_size;

    cudaFuncSetAttribute(fused_kernel,
                         cudaFuncAttributeMaxDynamicSharedMemorySize, DPDYN);

    binit_kernel<<<256, 256>>>();
    norms_kernel<<<8192, 256>>>(pred, targ);
    fused_kernel<<<2080, 256, DPDYN>>>(pred, targ);
    reduce_kernel<<<1, 32>>>((float*)d_out);
}

// round 14
// speedup vs baseline: 1.5797x; 1.1956x over previous
#include <cuda_runtime.h>
#include <cuda_fp16.h>
#include <math.h>

#define TINF 3.0e38f
#define TT   1024
#define BB   32
#define DDIM 64
#define RS   1024        // halves per diag row
#define DROWS 2048       // rows 0..2046 used; predicate caps loads at 2047
#define INF2 0x7C007C00u // half2 (+inf, +inf)

// Diag-major SQUARED cost [b][d][j] in fp16 (DP runs on d^2; sqrt on the final
// per-batch scalar). Valid cells written by cost role; 2 boundary cells per row
// pre-set +inf by binit. Deep-invalid cells unreachable (fmin/fmax NaN-safe).
__device__ __half g_cost[(size_t)BB * DROWS * RS];
__device__ float g_n2[2 * BB * TT];
__device__ float g_bdist[BB];
__device__ int   g_cnt[BB * 15];     // finished tiles per (batch, tile-antidiag)

// Tile visit order: (it,jt) sorted by g=it+jt (it*8+jt encoded).
__device__ const unsigned char g_order[64] = {
    0,
    1, 8,
    2, 9, 16,
    3, 10, 17, 24,
    4, 11, 18, 25, 32,
    5, 12, 19, 26, 33, 40,
    6, 13, 20, 27, 34, 41, 48,
    7, 14, 21, 28, 35, 42, 49, 56,
    15, 22, 29, 36, 43, 50, 57,
    23, 30, 37, 44, 51, 58,
    31, 38, 45, 52, 59,
    39, 46, 53, 60,
    47, 54, 61,
    55, 62,
    63
};

// ---------------------------------------------------------------------------
// Kernel 0: boundary-only init (+ zero the progress counters each launch).
// ---------------------------------------------------------------------------
__global__ void binit_kernel() {
    int i = blockIdx.x * blockDim.x + threadIdx.x;
    if (i < BB * 15) g_cnt[i] = 0;
    int b = i >> 11, d = i & 2047;
    if (b >= BB) return;
    unsigned short* row = (unsigned short*)(g_cost + ((size_t)b * DROWS + d) * RS);
    if (d <= 1022)                   row[d + 1]    = 0x7C00;
    else if (d >= 1024 && d <= 2046) row[d - 1024] = 0x7C00;
}

// ---------------------------------------------------------------------------
// Kernel 1: squared row norms. One warp per 64-dim row.
// ---------------------------------------------------------------------------
__global__ void norms_kernel(const float* __restrict__ pred,
                             const float* __restrict__ targ) {
    int gw   = (blockIdx.x * blockDim.x + threadIdx.x) >> 5;
    int lane = threadIdx.x & 31;
    if (gw >= 2 * BB * TT) return;
    const float* src = (gw < BB * TT) ? (pred + (size_t)gw * DDIM)
                                      : (targ + (size_t)(gw - BB * TT) * DDIM);
    float x0 = src[lane], x1 = src[lane + 32];
    float s = x0 * x0 + x1 * x1;
    #pragma unroll
    for (int o = 16; o > 0; o >>= 1) s += __shfl_down_sync(0xffffffffu, s, o);
    if (lane == 0) g_n2[gw] = s;
}

// ---------------------------------------------------------------------------
// TF32 mma helpers.
// ---------------------------------------------------------------------------
__device__ __forceinline__ unsigned f2tf(float x) {
    unsigned u;
    asm("cvt.rna.tf32.f32 %0, %1;" : "=r"(u) : "f"(x));
    return u;
}
__device__ __forceinline__ void mma_tf32(float c[4], const unsigned a[4],
                                         const unsigned b[2]) {
    asm volatile(
        "mma.sync.aligned.m16n8k8.row.col.f32.tf32.tf32.f32 "
        "{%0,%1,%2,%3}, {%4,%5,%6,%7}, {%8,%9}, {%0,%1,%2,%3};"
        : "+f"(c[0]), "+f"(c[1]), "+f"(c[2]), "+f"(c[3])
        : "r"(a[0]), "r"(a[1]), "r"(a[2]), "r"(a[3]), "r"(b[0]), "r"(b[1]));
}

#define SKP 36
#define RING    10
#define SROWH   1032                   // halves per staged row (4 guard + 1024 + 4 pad)
#define SSTAGEH (4 * SROWH)
#define DPDYN   (RING * SSTAGEH * 2)   // 82,560 B dynamic -> 2 CTAs/SM

__device__ __forceinline__ void cpa8(unsigned dst, const __half* src) {
    asm volatile("cp.async.ca.shared.global [%0], [%1], 8;"
                 :: "r"(dst), "l"(src));
}

// half2 min/max on raw uints (NaN-discarding, exact selection).
__device__ __forceinline__ unsigned hmin2u(unsigned a, unsigned b) {
    __half2 r = __hmin2(*(__half2*)&a, *(__half2*)&b);
    return *(unsigned*)&r;
}
__device__ __forceinline__ unsigned hmax2u(unsigned a, unsigned b) {
    __half2 r = __hmax2(*(__half2*)&a, *(__half2*)&b);
    return *(unsigned*)&r;
}
// Misaligned pair (a.hi, b.lo) in one PRMT.
#define SH(a, b) __byte_perm((a), (b), 0x5432)

// ---------------------------------------------------------------------------
// Cost role: TF32 tiles -> fp16 d^2, diag-major (unchanged from R13).
// ---------------------------------------------------------------------------
__device__ void cost_role(char* dyn, const float* __restrict__ pred,
                          const float* __restrict__ targ, int cbid) {
    int b  = cbid & 31;
    int code = g_order[cbid >> 5];
    int it = code >> 3, jt = code & 7;
    int i0 = it * 128, j0 = jt * 128;
    const float* A  = pred + (size_t)b * TT * DDIM;
    const float* Bm = targ + (size_t)b * TT * DDIM;

    float* smbuf = (float*)dyn;
    float* sA = smbuf;
    float* sB = smbuf + 128 * SKP;
    float* Cs = smbuf;

    int tid  = threadIdx.x;
    int lane = tid & 31, w = tid >> 5;
    int g    = lane >> 2, tig = lane & 3;
    int wm   = (w & 3) * 32, wn = (w >> 2) * 64;

    float c[2][8][4];
    #pragma unroll
    for (int mt = 0; mt < 2; ++mt)
        #pragma unroll
        for (int nt = 0; nt < 8; ++nt)
            #pragma unroll
            for (int e = 0; e < 4; ++e) c[mt][nt][e] = 0.f;

    int lr = tid >> 1;
    int lk = (tid & 1) * 16;
    const float* ga = A  + (size_t)(i0 + lr) * DDIM + lk;
    const float* gb = Bm + (size_t)(j0 + lr) * DDIM + lk;

    #pragma unroll 1
    for (int kc = 0; kc < 64; kc += 32) {
        #pragma unroll
        for (int c4 = 0; c4 < 4; ++c4) {
            float4 va = *(const float4*)(ga + kc + c4 * 4);
            float4 vb = *(const float4*)(gb + kc + c4 * 4);
            int o = lr * SKP + lk + c4 * 4;
            sA[o + 0] = __uint_as_float(f2tf(va.x));
            sA[o + 1] = __uint_as_float(f2tf(va.y));
            sA[o + 2] = __uint_as_float(f2tf(va.z));
            sA[o + 3] = __uint_as_float(f2tf(va.w));
            sB[o + 0] = __uint_as_float(f2tf(vb.x));
            sB[o + 1] = __uint_as_float(f2tf(vb.y));
            sB[o + 2] = __uint_as_float(f2tf(vb.z));
            sB[o + 3] = __uint_as_float(f2tf(vb.w));
        }
        __syncthreads();

        #pragma unroll
        for (int ks = 0; ks < 32; ks += 8) {
            unsigned af[2][4], bf[8][2];
            #pragma unroll
            for (int mt = 0; mt < 2; ++mt) {
                int mr = wm + mt * 16;
                af[mt][0] = __float_as_uint(sA[(mr + g)     * SKP + ks + tig]);
                af[mt][1] = __float_as_uint(sA[(mr + g + 8) * SKP + ks + tig]);
                af[mt][2] = __float_as_uint(sA[(mr + g)     * SKP + ks + tig + 4]);
                af[mt][3] = __float_as_uint(sA[(mr + g + 8) * SKP + ks + tig + 4]);
            }
            #pragma unroll
            for (int nt = 0; nt < 8; ++nt) {
                int nr = wn + nt * 8 + g;
                bf[nt][0] = __float_as_uint(sB[nr * SKP + ks + tig]);
                bf[nt][1] = __float_as_uint(sB[nr * SKP + ks + tig + 4]);
            }
            #pragma unroll
            for (int mt = 0; mt < 2; ++mt)
                #pragma unroll
                for (int nt = 0; nt < 8; ++nt)
                    mma_tf32(c[mt][nt], af[mt], bf[nt]);
        }
        __syncthreads();
    }

    float a2v[2][2], b2v[8][2];
    #pragma unroll
    for (int mt = 0; mt < 2; ++mt) {
        a2v[mt][0] = g_n2[b * TT + i0 + wm + mt * 16 + g];
        a2v[mt][1] = g_n2[b * TT + i0 + wm + mt * 16 + g + 8];
    }
    #pragma unroll
    for (int nt = 0; nt < 8; ++nt) {
        b2v[nt][0] = g_n2[BB * TT + b * TT + j0 + wn + nt * 8 + 2 * tig];
        b2v[nt][1] = g_n2[BB * TT + b * TT + j0 + wn + nt * 8 + 2 * tig + 1];
    }

    __half* out = g_cost + (size_t)b * DROWS * RS;

    #pragma unroll 1
    for (int qq = 0; qq < 4; ++qq) {
        int qi = qq >> 1, qj = qq & 1;
        __syncthreads();
        if ((w >> 2) == qj && ((w & 3) >> 1) == qi) {
            int mloc0 = ((w & 3) & 1) * 32;
            #pragma unroll
            for (int mt = 0; mt < 2; ++mt) {
                int ml = mloc0 + mt * 16 + g;
                #pragma unroll
                for (int nt = 0; nt < 8; ++nt) {
                    int nl = nt * 8 + 2 * tig;
                    float s0 = a2v[mt][0] + b2v[nt][0] - 2.0f * c[mt][nt][0];
                    float s1 = a2v[mt][0] + b2v[nt][1] - 2.0f * c[mt][nt][1];
                    float s2 = a2v[mt][1] + b2v[nt][0] - 2.0f * c[mt][nt][2];
                    float s3 = a2v[mt][1] + b2v[nt][1] - 2.0f * c[mt][nt][3];
                    Cs[ml * 66 + nl]           = fmaxf(s0, 1e-12f);
                    Cs[ml * 66 + nl + 1]       = fmaxf(s1, 1e-12f);
                    Cs[(ml + 8) * 66 + nl]     = fmaxf(s2, 1e-12f);
                    Cs[(ml + 8) * 66 + nl + 1] = fmaxf(s3, 1e-12f);
                }
            }
        }
        __syncthreads();

        int i0q = i0 + qi * 64, j0q = j0 + qj * 64;
        int D0 = i0q + j0q;
        for (int dd = w; dd < 127; dd += 8) {
            int jl = max(0, dd - 63);
            int jh = min(dd, 63);
            int L = jh - jl + 1;
            size_t gbase = (size_t)(D0 + dd) * RS + (size_t)(j0q + jl);
            for (int l = lane; l < L; l += 32) {
                int j = jl + l;
                out[gbase + l] = __float2half(Cs[(dd - j) * 66 + j]);
            }
        }
    }

    __threadfence();
    __syncthreads();
    if (tid == 0) atomicAdd(&g_cnt[b * 15 + (it + jt)], 1);
}

// ---------------------------------------------------------------------------
// DP role: superstep math in packed fp16x2 (HMNMX2 + PRMT shifts). Selection
// in fp16 is BIT-IDENTICAL to converting to fp32 and selecting (monotone
// conversion; all values are cost elements or +-inf). No F2F conversions,
// halo = 4 packed shfls, mailbox = one uint4. Ring/predication/counters
// unchanged from R13.
// ---------------------------------------------------------------------------
__device__ void dp_role(char* dyn) {
    __half* dsmh = (__half*)dyn;
    int b    = blockIdx.x;
    int t    = threadIdx.x;
    int w    = t >> 5;
    int lane = t & 31;
    int j0   = t << 2;
    const __half* SC = g_cost + (size_t)b * DROWS * RS;

    __shared__ uint4 swpq[2][8];   // per-warp boundary: (p01,p23,q01,q23)
    if (t < 16) ((uint4*)swpq)[t] = make_uint4(INF2, INF2, INF2, INF2);
    for (int i = t; i < RING * 4; i += 256) {
        unsigned* gr = (unsigned*)(dsmh + i * SROWH);
        gr[0] = INF2; gr[1] = INF2;
    }
    __syncthreads();

    unsigned smu = (unsigned)__cvta_generic_to_shared(dsmh) + (unsigned)(4 + j0) * 2;

    #define DP_ON(d) ((unsigned)((d) - j0 + 1) <= 1028u)

    // Availability: rows <= 128*G+127 ready once all tile-groups <= G done.
    int done_groups = 0;
    const volatile int* cnt = (const volatile int*)(g_cnt + b * 15);
    while (done_groups <= 0) {
        if (cnt[0] >= 1) done_groups = 1;
    }
    __threadfence();

    for (int s = 0; s < RING - 1; ++s) {
        const __half* src = SC + (size_t)(4 * s) * RS + j0;
        unsigned d = smu + s * (SSTAGEH * 2);
        #pragma unroll
        for (int k = 0; k < 4; ++k)
            if (DP_ON(4 * s + k)) cpa8(d + k * (SROWH * 2), src + (size_t)k * RS);
        asm volatile("cp.async.commit_group;");
    }

    unsigned p01 = INF2, p23 = INF2;   // own cols (j0..j0+3), diag d0-1
    unsigned q01 = INF2, q23 = INF2;   // diag d0-2
    float res  = 0.f;
    int stage  = 0;

    #pragma unroll 1
    for (int s = 0; s < 512; ++s) {
        asm volatile("cp.async.wait_group 8;");
        __syncthreads();

        const __half* bp = dsmh + stage * SSTAGEH;
        unsigned C0[4], C1[4], C2[4], C3[4];
        {
            uint2 hv, ov;
            hv = *(const uint2*)(bp + 0 * SROWH + j0);
            ov = *(const uint2*)(bp + 0 * SROWH + j0 + 4);
            C0[0] = hv.x; C0[1] = hv.y; C0[2] = ov.x; C0[3] = ov.y;
            hv = *(const uint2*)(bp + 1 * SROWH + j0);
            ov = *(const uint2*)(bp + 1 * SROWH + j0 + 4);
            C1[0] = hv.x; C1[1] = hv.y; C1[2] = ov.x; C1[3] = ov.y;
            hv = *(const uint2*)(bp + 2 * SROWH + j0);
            ov = *(const uint2*)(bp + 2 * SROWH + j0 + 4);
            C2[0] = hv.x; C2[1] = hv.y; C2[2] = ov.x; C2[3] = ov.y;
            hv = *(const uint2*)(bp + 3 * SROWH + j0);
            ov = *(const uint2*)(bp + 3 * SROWH + j0 + 4);
            C3[0] = hv.x; C3[1] = hv.y; C3[2] = ov.x; C3[3] = ov.y;
        }

        // Halo: left neighbor's own pairs (their registers hold last superstep).
        unsigned hp01 = __shfl_up_sync(0xffffffffu, p01, 1);
        unsigned hp23 = __shfl_up_sync(0xffffffffu, p23, 1);
        unsigned hq01 = __shfl_up_sync(0xffffffffu, q01, 1);
        unsigned hq23 = __shfl_up_sync(0xffffffffu, q23, 1);
        if (lane == 0) {
            if (w == 0) {
                hp01 = hp23 = hq01 = INF2;
                // seed: virtual ca[-1][-1] = -inf in high half (col j0-1) at s=0
                hq23 = (s == 0) ? 0xFC007C00u : INF2;
            } else {
                uint4 m = swpq[s & 1][w - 1];
                hp01 = m.x; hp23 = m.y; hq01 = m.z; hq23 = m.w;
            }
        }

        // Extended 8-wide rows as 4 half2 pairs; pair k = cols (2k, 2k+1),
        // own cols at extended idx 4..7 (pairs 2,3).
        unsigned P[4] = {hp01, hp23, p01, p23};
        unsigned Q[4] = {hq01, hq23, q01, q23};
        unsigned Ps[4] = {SH(INF2, P[0]), SH(P[0], P[1]), SH(P[1], P[2]), SH(P[2], P[3])};
        unsigned Qs[4] = {SH(INF2, Q[0]), SH(Q[0], Q[1]), SH(Q[1], Q[2]), SH(Q[2], Q[3])};

        unsigned L0[4], L1[4], L2[4], L3[4];
        #pragma unroll
        for (int k = 0; k < 4; ++k)
            L0[k] = hmax2u(C0[k], hmin2u(hmin2u(P[k], Ps[k]), Qs[k]));
        unsigned L0s[4] = {SH(INF2, L0[0]), SH(L0[0], L0[1]), SH(L0[1], L0[2]), SH(L0[2], L0[3])};
        #pragma unroll
        for (int k = 0; k < 4; ++k)
            L1[k] = hmax2u(C1[k], hmin2u(hmin2u(L0[k], L0s[k]), Ps[k]));
        unsigned L1s[4] = {SH(INF2, L1[0]), SH(L1[0], L1[1]), SH(L1[1], L1[2]), SH(L1[2], L1[3])};
        #pragma unroll
        for (int k = 0; k < 4; ++k)
            L2[k] = hmax2u(C2[k], hmin2u(hmin2u(L1[k], L1s[k]), L0s[k]));
        unsigned L2s[4] = {SH(INF2, L2[0]), SH(L2[0], L2[1]), SH(L2[1], L2[2]), SH(L2[2], L2[3])};
        #pragma unroll
        for (int k = 0; k < 4; ++k)
            L3[k] = hmax2u(C3[k], hmin2u(hmin2u(L2[k], L2s[k]), L1s[k]));

        if (lane == 31)
            swpq[(s + 1) & 1][w] = make_uint4(L3[2], L3[3], L2[2], L2[3]);
        if (s == 511) res = __high2float(*(__half2*)&L2[3]);   // diag 2046, col 1023

        p01 = L3[2]; p23 = L3[3]; q01 = L2[2]; q23 = L2[3];

        // Availability for rows about to be issued (rows <= 4s+39).
        {
            int gneed = (4 * s + 39) >> 7;
            if (gneed > 14) gneed = 14;
            if (done_groups <= gneed) {
                while (done_groups <= gneed) {
                    int tn = (done_groups <= 7) ? done_groups + 1 : 15 - done_groups;
                    if (cnt[done_groups] >= tn) ++done_groups;
                }
                __threadfence();
            }
        }

        {
            int st2 = stage + (RING - 1); if (st2 >= RING) st2 -= RING;
            int dbase = 4 * (s + RING - 1);
            const __half* src = SC + (size_t)dbase * RS + j0;
            unsigned d = smu + st2 * (SSTAGEH * 2);
            #pragma unroll
            for (int k = 0; k < 4; ++k)
                if (DP_ON(dbase + k)) cpa8(d + k * (SROWH * 2), src + (size_t)k * RS);
            asm volatile("cp.async.commit_group;");
        }
        if (++stage == RING) stage = 0;
    }

    if (t == 255) g_bdist[b] = res;
    #undef DP_ON
}

// ---------------------------------------------------------------------------
// Fused kernel: bids 0..31 = DP consumers (wave-1 resident; never block
// producers => no deadlock), bids 32..2079 = cost producers.
// ---------------------------------------------------------------------------
__global__ void __launch_bounds__(256, 2) fused_kernel(const float* __restrict__ pred,
                                                       const float* __restrict__ targ) {
    extern __shared__ __align__(16) char dyn[];
    if (blockIdx.x < 32) dp_role(dyn);
    else                 cost_role(dyn, pred, targ, blockIdx.x - 32);
}

// ---------------------------------------------------------------------------
// Kernel 4: sqrt of per-batch squared Frechet, then mean.
// ---------------------------------------------------------------------------
__global__ void reduce_kernel(float* out) {
    float v = sqrtf(g_bdist[threadIdx.x]);
    #pragma unroll
    for (int o = 16; o > 0; o >>= 1) v += __shfl_down_sync(0xffffffffu, v, o);
    if (threadIdx.x == 0) out[0] = v * (1.0f / BB);
}

// ---------------------------------------------------------------------------
extern "C" void kernel_launch(void* const* d_in, const int* in_sizes, int n_in,
                              void* d_out, int out_size) {
    const float* pred = (const float*)d_in[0];
    const float* targ = (const float*)d_in[1];
    (void)in_sizes; (void)n_in; (void)out_size;

    cudaFuncSetAttribute(fused_kernel,
                         cudaFuncAttributeMaxDynamicSharedMemorySize, DPDYN);

    binit_kernel<<<256, 256>>>();
    norms_kernel<<<8192, 256>>>(pred, targ);
    fused_kernel<<<2080, 256, DPDYN>>>(pred, targ);
    reduce_kernel<<<1, 32>>>((float*)d_out);
}

// round 15
// speedup vs baseline: 1.6044x; 1.0156x over previous
#include <cuda_runtime.h>
#include <cuda_fp16.h>
#include <math.h>

#define TINF 3.0e38f
#define TT   1024
#define BB   32
#define DDIM 64
#define RS   1024        // halves per diag row
#define DROWS 2048       // rows 0..2046 used; predicate caps loads at 2047
#define INF2 0x7C007C00u // half2 (+inf, +inf)

// Diag-major SQUARED cost [b][d][j] in fp16 (DP runs on d^2; sqrt on the final
// per-batch scalar). Valid cells written by cost role; 2 boundary cells per row
// pre-set +inf by binit. Deep-invalid cells unreachable (fmin/fmax NaN-safe).
__device__ __half g_cost[(size_t)BB * DROWS * RS];
__device__ float g_n2[2 * BB * TT];
__device__ float g_bdist[BB];
__device__ int   g_cnt[BB * 15];     // finished tiles per (batch, tile-antidiag)

// Tile visit order: (it,jt) sorted by g=it+jt (it*8+jt encoded).
__device__ const unsigned char g_order[64] = {
    0,
    1, 8,
    2, 9, 16,
    3, 10, 17, 24,
    4, 11, 18, 25, 32,
    5, 12, 19, 26, 33, 40,
    6, 13, 20, 27, 34, 41, 48,
    7, 14, 21, 28, 35, 42, 49, 56,
    15, 22, 29, 36, 43, 50, 57,
    23, 30, 37, 44, 51, 58,
    31, 38, 45, 52, 59,
    39, 46, 53, 60,
    47, 54, 61,
    55, 62,
    63
};

// ---------------------------------------------------------------------------
// Kernel 0: boundary-only init (+ zero the progress counters each launch).
// ---------------------------------------------------------------------------
__global__ void binit_kernel() {
    int i = blockIdx.x * blockDim.x + threadIdx.x;
    if (i < BB * 15) g_cnt[i] = 0;
    int b = i >> 11, d = i & 2047;
    if (b >= BB) return;
    unsigned short* row = (unsigned short*)(g_cost + ((size_t)b * DROWS + d) * RS);
    if (d <= 1022)                   row[d + 1]    = 0x7C00;
    else if (d >= 1024 && d <= 2046) row[d - 1024] = 0x7C00;
}

// ---------------------------------------------------------------------------
// Kernel 1: squared row norms. One warp per 64-dim row.
// ---------------------------------------------------------------------------
__global__ void norms_kernel(const float* __restrict__ pred,
                             const float* __restrict__ targ) {
    int gw   = (blockIdx.x * blockDim.x + threadIdx.x) >> 5;
    int lane = threadIdx.x & 31;
    if (gw >= 2 * BB * TT) return;
    const float* src = (gw < BB * TT) ? (pred + (size_t)gw * DDIM)
                                      : (targ + (size_t)(gw - BB * TT) * DDIM);
    float x0 = src[lane], x1 = src[lane + 32];
    float s = x0 * x0 + x1 * x1;
    #pragma unroll
    for (int o = 16; o > 0; o >>= 1) s += __shfl_down_sync(0xffffffffu, s, o);
    if (lane == 0) g_n2[gw] = s;
}

// ---------------------------------------------------------------------------
// TF32 mma helpers.
// ---------------------------------------------------------------------------
__device__ __forceinline__ unsigned f2tf(float x) {
    unsigned u;
    asm("cvt.rna.tf32.f32 %0, %1;" : "=r"(u) : "f"(x));
    return u;
}
__device__ __forceinline__ void mma_tf32(float c[4], const unsigned a[4],
                                         const unsigned b[2]) {
    asm volatile(
        "mma.sync.aligned.m16n8k8.row.col.f32.tf32.tf32.f32 "
        "{%0,%1,%2,%3}, {%4,%5,%6,%7}, {%8,%9}, {%0,%1,%2,%3};"
        : "+f"(c[0]), "+f"(c[1]), "+f"(c[2]), "+f"(c[3])
        : "r"(a[0]), "r"(a[1]), "r"(a[2]), "r"(a[3]), "r"(b[0]), "r"(b[1]));
}

#define SKP 36
#define RING    6
#define SROWH   1036                   // halves per staged row (8 guard + 1024 + 4 pad)
#define SSTAGEH (8 * SROWH)            // 8 rows per stage
#define DPDYN   (RING * SSTAGEH * 2)   // 99,456 B dynamic -> 2 CTAs/SM

__device__ __forceinline__ void cpa8(unsigned dst, const __half* src) {
    asm volatile("cp.async.ca.shared.global [%0], [%1], 8;"
                 :: "r"(dst), "l"(src));
}

// half2 min/max on raw uints (NaN-discarding, exact selection).
__device__ __forceinline__ unsigned hmin2u(unsigned a, unsigned b) {
    __half2 r = __hmin2(*(__half2*)&a, *(__half2*)&b);
    return *(unsigned*)&r;
}
__device__ __forceinline__ unsigned hmax2u(unsigned a, unsigned b) {
    __half2 r = __hmax2(*(__half2*)&a, *(__half2*)&b);
    return *(unsigned*)&r;
}
// Misaligned pair (a.hi, b.lo) in one PRMT.
#define SH(a, b) __byte_perm((a), (b), 0x5432)

// ---------------------------------------------------------------------------
// Cost role: TF32 tiles -> fp16 d^2, diag-major (unchanged from R13/R14).
// ---------------------------------------------------------------------------
__device__ void cost_role(char* dyn, const float* __restrict__ pred,
                          const float* __restrict__ targ, int cbid) {
    int b  = cbid & 31;
    int code = g_order[cbid >> 5];
    int it = code >> 3, jt = code & 7;
    int i0 = it * 128, j0 = jt * 128;
    const float* A  = pred + (size_t)b * TT * DDIM;
    const float* Bm = targ + (size_t)b * TT * DDIM;

    float* smbuf = (float*)dyn;
    float* sA = smbuf;
    float* sB = smbuf + 128 * SKP;
    float* Cs = smbuf;

    int tid  = threadIdx.x;
    int lane = tid & 31, w = tid >> 5;
    int g    = lane >> 2, tig = lane & 3;
    int wm   = (w & 3) * 32, wn = (w >> 2) * 64;

    float c[2][8][4];
    #pragma unroll
    for (int mt = 0; mt < 2; ++mt)
        #pragma unroll
        for (int nt = 0; nt < 8; ++nt)
            #pragma unroll
            for (int e = 0; e < 4; ++e) c[mt][nt][e] = 0.f;

    int lr = tid >> 1;
    int lk = (tid & 1) * 16;
    const float* ga = A  + (size_t)(i0 + lr) * DDIM + lk;
    const float* gb = Bm + (size_t)(j0 + lr) * DDIM + lk;

    #pragma unroll 1
    for (int kc = 0; kc < 64; kc += 32) {
        #pragma unroll
        for (int c4 = 0; c4 < 4; ++c4) {
            float4 va = *(const float4*)(ga + kc + c4 * 4);
            float4 vb = *(const float4*)(gb + kc + c4 * 4);
            int o = lr * SKP + lk + c4 * 4;
            sA[o + 0] = __uint_as_float(f2tf(va.x));
            sA[o + 1] = __uint_as_float(f2tf(va.y));
            sA[o + 2] = __uint_as_float(f2tf(va.z));
            sA[o + 3] = __uint_as_float(f2tf(va.w));
            sB[o + 0] = __uint_as_float(f2tf(vb.x));
            sB[o + 1] = __uint_as_float(f2tf(vb.y));
            sB[o + 2] = __uint_as_float(f2tf(vb.z));
            sB[o + 3] = __uint_as_float(f2tf(vb.w));
        }
        __syncthreads();

        #pragma unroll
        for (int ks = 0; ks < 32; ks += 8) {
            unsigned af[2][4], bf[8][2];
            #pragma unroll
            for (int mt = 0; mt < 2; ++mt) {
                int mr = wm + mt * 16;
                af[mt][0] = __float_as_uint(sA[(mr + g)     * SKP + ks + tig]);
                af[mt][1] = __float_as_uint(sA[(mr + g + 8) * SKP + ks + tig]);
                af[mt][2] = __float_as_uint(sA[(mr + g)     * SKP + ks + tig + 4]);
                af[mt][3] = __float_as_uint(sA[(mr + g + 8) * SKP + ks + tig + 4]);
            }
            #pragma unroll
            for (int nt = 0; nt < 8; ++nt) {
                int nr = wn + nt * 8 + g;
                bf[nt][0] = __float_as_uint(sB[nr * SKP + ks + tig]);
                bf[nt][1] = __float_as_uint(sB[nr * SKP + ks + tig + 4]);
            }
            #pragma unroll
            for (int mt = 0; mt < 2; ++mt)
                #pragma unroll
                for (int nt = 0; nt < 8; ++nt)
                    mma_tf32(c[mt][nt], af[mt], bf[nt]);
        }
        __syncthreads();
    }

    float a2v[2][2], b2v[8][2];
    #pragma unroll
    for (int mt = 0; mt < 2; ++mt) {
        a2v[mt][0] = g_n2[b * TT + i0 + wm + mt * 16 + g];
        a2v[mt][1] = g_n2[b * TT + i0 + wm + mt * 16 + g + 8];
    }
    #pragma unroll
    for (int nt = 0; nt < 8; ++nt) {
        b2v[nt][0] = g_n2[BB * TT + b * TT + j0 + wn + nt * 8 + 2 * tig];
        b2v[nt][1] = g_n2[BB * TT + b * TT + j0 + wn + nt * 8 + 2 * tig + 1];
    }

    __half* out = g_cost + (size_t)b * DROWS * RS;

    #pragma unroll 1
    for (int qq = 0; qq < 4; ++qq) {
        int qi = qq >> 1, qj = qq & 1;
        __syncthreads();
        if ((w >> 2) == qj && ((w & 3) >> 1) == qi) {
            int mloc0 = ((w & 3) & 1) * 32;
            #pragma unroll
            for (int mt = 0; mt < 2; ++mt) {
                int ml = mloc0 + mt * 16 + g;
                #pragma unroll
                for (int nt = 0; nt < 8; ++nt) {
                    int nl = nt * 8 + 2 * tig;
                    float s0 = a2v[mt][0] + b2v[nt][0] - 2.0f * c[mt][nt][0];
                    float s1 = a2v[mt][0] + b2v[nt][1] - 2.0f * c[mt][nt][1];
                    float s2 = a2v[mt][1] + b2v[nt][0] - 2.0f * c[mt][nt][2];
                    float s3 = a2v[mt][1] + b2v[nt][1] - 2.0f * c[mt][nt][3];
                    Cs[ml * 66 + nl]           = fmaxf(s0, 1e-12f);
                    Cs[ml * 66 + nl + 1]       = fmaxf(s1, 1e-12f);
                    Cs[(ml + 8) * 66 + nl]     = fmaxf(s2, 1e-12f);
                    Cs[(ml + 8) * 66 + nl + 1] = fmaxf(s3, 1e-12f);
                }
            }
        }
        __syncthreads();

        int i0q = i0 + qi * 64, j0q = j0 + qj * 64;
        int D0 = i0q + j0q;
        for (int dd = w; dd < 127; dd += 8) {
            int jl = max(0, dd - 63);
            int jh = min(dd, 63);
            int L = jh - jl + 1;
            size_t gbase = (size_t)(D0 + dd) * RS + (size_t)(j0q + jl);
            for (int l = lane; l < L; l += 32) {
                int j = jl + l;
                out[gbase + l] = __float2half(Cs[(dd - j) * 66 + j]);
            }
        }
    }

    __threadfence();
    __syncthreads();
    if (tid == 0) atomicAdd(&g_cnt[b * 15 + (it + jt)], 1);
}

// ---------------------------------------------------------------------------
// DP role: EIGHT diagonals per superstep (256 barriers instead of 512).
// Extended window 12 cols = 6 half2 pairs, 8 levels of the identical fp16x2
// recurrence. Halo: shfl_up 1 (t-1) + shfl_up 2 (t-2); lanes 0/1 patched from
// a warp mailbox carrying lanes 30+31 state. Stage = 8 rows, RING=6,
// wait_group 4. Bit-identical selection => rel_err must stay 8.989491e-06.
// ---------------------------------------------------------------------------
__device__ void dp_role(char* dyn) {
    __half* dsmh = (__half*)dyn;
    int b    = blockIdx.x;
    int t    = threadIdx.x;
    int w    = t >> 5;
    int lane = t & 31;
    int j0   = t << 2;
    const __half* SC = g_cost + (size_t)b * DROWS * RS;

    __shared__ uint4 swm[2][8][2];   // [buf][warp][lane-30]: (p01,p23,q01,q23)
    if (t < 32) ((uint4*)swm)[t] = make_uint4(INF2, INF2, INF2, INF2);
    for (int i = t; i < RING * 8; i += 256) {       // 8-half +inf guards per row
        unsigned* gr = (unsigned*)(dsmh + i * SROWH);
        gr[0] = INF2; gr[1] = INF2; gr[2] = INF2; gr[3] = INF2;
    }
    __syncthreads();

    unsigned smu = (unsigned)__cvta_generic_to_shared(dsmh) + (unsigned)(8 + j0) * 2;

    #define DP_ON(d) ((unsigned)((d) - j0 + 1) <= 1028u)

    // Availability: rows <= 128*G+127 ready once all tile-groups <= G done.
    int done_groups = 0;
    const volatile int* cnt = (const volatile int*)(g_cnt + b * 15);
    while (done_groups <= 0) {
        if (cnt[0] >= 1) done_groups = 1;
    }
    __threadfence();

    // Prologue: stages 0..4 (rows 0..39, group 0 only).
    for (int st = 0; st < RING - 1; ++st) {
        #pragma unroll
        for (int k = 0; k < 8; ++k)
            if (DP_ON(8 * st + k))
                cpa8(smu + (st * 8 + k) * (SROWH * 2),
                     SC + (size_t)(8 * st + k) * RS + j0);
        asm volatile("cp.async.commit_group;");
    }

    unsigned p01 = INF2, p23 = INF2;   // own cols (j0..j0+3), diag d0-1
    unsigned q01 = INF2, q23 = INF2;   // diag d0-2
    float res  = 0.f;
    int stage  = 0;

    // 256 supersteps x 8 diagonals = 2048 (res latched at s=255, level 6 = diag 2046).
    #pragma unroll 1
    for (int s = 0; s < 256; ++s) {
        asm volatile("cp.async.wait_group 4;");
        __syncthreads();

        const __half* bp = dsmh + stage * SSTAGEH;

        // Halo from t-1 (pairs 2,3) and t-2 (pairs 0,1).
        unsigned s1p01 = __shfl_up_sync(0xffffffffu, p01, 1);
        unsigned s1p23 = __shfl_up_sync(0xffffffffu, p23, 1);
        unsigned s1q01 = __shfl_up_sync(0xffffffffu, q01, 1);
        unsigned s1q23 = __shfl_up_sync(0xffffffffu, q23, 1);
        unsigned s2p01 = __shfl_up_sync(0xffffffffu, p01, 2);
        unsigned s2p23 = __shfl_up_sync(0xffffffffu, p23, 2);
        unsigned s2q01 = __shfl_up_sync(0xffffffffu, q01, 2);
        unsigned s2q23 = __shfl_up_sync(0xffffffffu, q23, 2);
        if (lane <= 1) {
            if (w == 0) {
                s2p01 = s2p23 = s2q01 = s2q23 = INF2;
                if (lane == 0) {
                    s1p01 = s1p23 = s1q01 = INF2;
                    s1q23 = (s == 0) ? 0xFC007C00u : INF2;   // seed ca[-1][-1]
                }
            } else {
                uint4 m31 = swm[s & 1][w - 1][1];
                if (lane == 0) {
                    uint4 m30 = swm[s & 1][w - 1][0];
                    s2p01 = m30.x; s2p23 = m30.y; s2q01 = m30.z; s2q23 = m30.w;
                    s1p01 = m31.x; s1p23 = m31.y; s1q01 = m31.z; s1q23 = m31.w;
                } else {   // lane 1: t-2 = warp w-1 lane 31
                    s2p01 = m31.x; s2p23 = m31.y; s2q01 = m31.z; s2q23 = m31.w;
                }
            }
        }

        unsigned a1[6]  = {s2p01, s2p23, s1p01, s1p23, p01, p23};   // prev1 = P
        unsigned Qv[6]  = {s2q01, s2q23, s1q01, s1q23, q01, q23};
        unsigned a1s[6], a2s[6];                                    // P>>1, Q>>1
        a1s[0] = SH(INF2, a1[0]);
        a2s[0] = SH(INF2, Qv[0]);
        #pragma unroll
        for (int k = 1; k < 6; ++k) {
            a1s[k] = SH(a1[k-1], a1[k]);
            a2s[k] = SH(Qv[k-1], Qv[k]);
        }

        unsigned nq01 = INF2, nq23 = INF2;   // level 6 own pairs (new q)
        #pragma unroll
        for (int l = 0; l < 8; ++l) {
            const __half* rp = bp + l * SROWH + j0;
            uint2 c0 = *(const uint2*)(rp);
            uint2 c1 = *(const uint2*)(rp + 4);
            uint2 c2 = *(const uint2*)(rp + 8);
            unsigned C[6] = {c0.x, c0.y, c1.x, c1.y, c2.x, c2.y};

            unsigned cur[6];
            #pragma unroll
            for (int k = 0; k < 6; ++k)
                cur[k] = hmax2u(C[k], hmin2u(hmin2u(a1[k], a1s[k]), a2s[k]));

            unsigned curs0 = SH(INF2, cur[0]);
            a2s[0] = a1s[0]; a1s[0] = curs0; a1[0] = cur[0];
            #pragma unroll
            for (int k = 1; k < 6; ++k) {
                unsigned cs = SH(cur[k-1], cur[k]);
                a2s[k] = a1s[k]; a1s[k] = cs; a1[k] = cur[k];
            }
            if (l == 6) { nq01 = cur[4]; nq23 = cur[5]; }
        }

        p01 = a1[4]; p23 = a1[5]; q01 = nq01; q23 = nq23;

        if (lane >= 30)
            swm[(s + 1) & 1][w][lane - 30] = make_uint4(p01, p23, q01, q23);
        if (s == 255) res = __high2float(*(__half2*)&nq23);   // diag 2046, col 1023

        // Availability for rows about to be issued (rows <= 8s+47).
        {
            int gneed = (8 * s + 47) >> 7;
            if (gneed > 14) gneed = 14;
            if (done_groups <= gneed) {
                while (done_groups <= gneed) {
                    int tn = (done_groups <= 7) ? done_groups + 1 : 15 - done_groups;
                    if (cnt[done_groups] >= tn) ++done_groups;
                }
                __threadfence();
            }
        }

        // Issue stage s+5 into the buffer consumed at body s-1 (race-free).
        {
            int st2 = stage + (RING - 1); if (st2 >= RING) st2 -= RING;
            int dbase = 8 * (s + RING - 1);
            #pragma unroll
            for (int k = 0; k < 8; ++k)
                if (DP_ON(dbase + k))
                    cpa8(smu + (st2 * 8 + k) * (SROWH * 2),
                         SC + (size_t)(dbase + k) * RS + j0);
            asm volatile("cp.async.commit_group;");
        }
        if (++stage == RING) stage = 0;
    }

    if (t == 255) g_bdist[b] = res;
    #undef DP_ON
}

// ---------------------------------------------------------------------------
// Fused kernel: bids 0..31 = DP consumers (wave-1 resident; never block
// producers => no deadlock), bids 32..2079 = cost producers.
// ---------------------------------------------------------------------------
__global__ void __launch_bounds__(256, 2) fused_kernel(const float* __restrict__ pred,
                                                       const float* __restrict__ targ) {
    extern __shared__ __align__(16) char dyn[];
    if (blockIdx.x < 32) dp_role(dyn);
    else                 cost_role(dyn, pred, targ, blockIdx.x - 32);
}

// ---------------------------------------------------------------------------
// Kernel 4: sqrt of per-batch squared Frechet, then mean.
// ---------------------------------------------------------------------------
__global__ void reduce_kernel(float* out) {
    float v = sqrtf(g_bdist[threadIdx.x]);
    #pragma unroll
    for (int o = 16; o > 0; o >>= 1) v += __shfl_down_sync(0xffffffffu, v, o);
    if (threadIdx.x == 0) out[0] = v * (1.0f / BB);
}

// ---------------------------------------------------------------------------
extern "C" void kernel_launch(void* const* d_in, const int* in_sizes, int n_in,
                              void* d_out, int out_size) {
    const float* pred = (const float*)d_in[0];
    const float* targ = (const float*)d_in[1];
    (void)in_sizes; (void)n_in; (void)out_size;

    cudaFuncSetAttribute(fused_kernel,
                         cudaFuncAttributeMaxDynamicSharedMemorySize, DPDYN);

    binit_kernel<<<256, 256>>>();
    norms_kernel<<<8192, 256>>>(pred, targ);
    fused_kernel<<<2080, 256, DPDYN>>>(pred, targ);
    reduce_kernel<<<1, 32>>>((float*)d_out);
}